// round 3
// baseline (speedup 1.0000x reference)
#include <cuda_runtime.h>
#include <math.h>

#define B_ 2
#define S_ 1024
#define D_ 768
#define H_ 12
#define E_ 8
#define DH_ 64
#define DFF_ 2048
#define NTOK (B_*S_)
#define CAP_ 320
#define NOUT (NTOK*D_)

// ---------------- scratch (device globals; no allocation allowed) -------------
__device__ float g_xln [NTOK*D_];
__device__ float g_q   [NTOK*D_];
__device__ float g_k   [NTOK*D_];
__device__ float g_vsel[NTOK*D_];
__device__ float g_attn[NTOK*D_];
__device__ float g_x1  [NTOK*D_];
__device__ float g_xln2[NTOK*D_];
__device__ int   g_eidx[NTOK*H_];
__device__ int   g_hard[H_*E_];
__device__ float g_m[B_*H_*S_];
__device__ float g_l[B_*H_*S_];
__device__ int   g_tk_idx[NTOK*2];
__device__ float g_tk_prob[NTOK*2];
__device__ int   g_token_slot[NTOK*2];
__device__ int   g_slot_token[E_*CAP_];
__device__ float g_slot_w[E_*CAP_];
__device__ int   g_ecount[E_];
__device__ float g_hbuf[E_*CAP_*DFF_];   // ~21 MB
__device__ float g_sout[E_*CAP_*D_];     // ~7.9 MB

// ---------------- LayerNorm ---------------------------------------------------
__global__ void ln_kernel(const float* __restrict__ x, const float* __restrict__ g,
                          const float* __restrict__ b, float* __restrict__ out) {
    int row = blockIdx.x, tid = threadIdx.x;
    const float* xr = x + (size_t)row * D_;
    float s = 0.f, s2 = 0.f;
    for (int d = tid; d < D_; d += 256) { float v = xr[d]; s += v; s2 += v * v; }
    for (int o = 16; o > 0; o >>= 1) {
        s  += __shfl_down_sync(0xffffffffu, s,  o);
        s2 += __shfl_down_sync(0xffffffffu, s2, o);
    }
    __shared__ float sh[8], sh2[8];
    int w = tid >> 5, lane = tid & 31;
    if (lane == 0) { sh[w] = s; sh2[w] = s2; }
    __syncthreads();
    __shared__ float smean, sinv;
    if (tid == 0) {
        float a = 0.f, a2 = 0.f;
        for (int i = 0; i < 8; i++) { a += sh[i]; a2 += sh2[i]; }
        float mean = a / D_;
        float var  = a2 / D_ - mean * mean;
        smean = mean; sinv = rsqrtf(var + 1e-5f);
    }
    __syncthreads();
    float mean = smean, inv = sinv;
    for (int d = tid; d < D_; d += 256)
        out[(size_t)row * D_ + d] = (xr[d] - mean) * inv * g[d] + b[d];
}

// ---------------- plain SGEMM: C[M,N] = A[M,K] @ B[K,N] (all mult of tile) ----
__global__ void sgemm_nn(const float* __restrict__ A, const float* __restrict__ Bm,
                         float* __restrict__ C, int M, int N, int K) {
    __shared__ float As[16][65];
    __shared__ float Bs[16][64];
    int tid = threadIdx.x;
    int m0 = blockIdx.y * 64, n0 = blockIdx.x * 64;
    int rm = tid >> 4, cn = tid & 15;
    int ar = tid >> 2, ac = (tid & 3) << 2;
    int br = tid >> 4, bc = (tid & 15) << 2;
    float acc[4][4] = {};
    for (int k0 = 0; k0 < K; k0 += 16) {
        float4 a = *(const float4*)(A + (size_t)(m0 + ar) * K + k0 + ac);
        As[ac + 0][ar] = a.x; As[ac + 1][ar] = a.y;
        As[ac + 2][ar] = a.z; As[ac + 3][ar] = a.w;
        *(float4*)&Bs[br][bc] = *(const float4*)(Bm + (size_t)(k0 + br) * N + n0 + bc);
        __syncthreads();
#pragma unroll
        for (int k = 0; k < 16; k++) {
            float ra[4];
#pragma unroll
            for (int i = 0; i < 4; i++) ra[i] = As[k][rm * 4 + i];
            float4 b4 = *(float4*)&Bs[k][cn * 4];
            float rb[4] = { b4.x, b4.y, b4.z, b4.w };
#pragma unroll
            for (int i = 0; i < 4; i++)
#pragma unroll
                for (int j = 0; j < 4; j++) acc[i][j] += ra[i] * rb[j];
        }
        __syncthreads();
    }
#pragma unroll
    for (int i = 0; i < 4; i++)
#pragma unroll
        for (int j = 0; j < 4; j++)
            C[(size_t)(m0 + rm * 4 + i) * N + n0 + cn * 4 + j] = acc[i][j];
}

// ---------------- attention router: argmax expert per (token, head) -----------
__global__ void zero_hard() { int i = threadIdx.x; if (i < H_ * E_) g_hard[i] = 0; }

__global__ void router_kernel(const float* __restrict__ Wr) {
    int row = blockIdx.x, tid = threadIdx.x; // 128
    __shared__ float xr[D_];
    __shared__ float lg[H_ * E_];
    for (int d = tid; d < D_; d += 128) xr[d] = g_xln[(size_t)row * D_ + d];
    __syncthreads();
    if (tid < H_ * E_) {
        float acc = 0.f;
        for (int d = 0; d < D_; d++) acc += xr[d] * Wr[(size_t)d * (H_ * E_) + tid];
        lg[tid] = acc;
    }
    __syncthreads();
    if (tid < H_) {
        int h = tid;
        float best = lg[h * E_]; int bi = 0;
        for (int e = 1; e < E_; e++) { float v = lg[h * E_ + e]; if (v > best) { best = v; bi = e; } }
        g_eidx[row * H_ + h] = bi;
        atomicAdd(&g_hard[h * E_ + bi], 1);
    }
}

// ---------------- per (token, head) expert matvecs ----------------------------
__global__ void vsel_kernel(const float* __restrict__ Wv) {
    int row = blockIdx.x, tid = threadIdx.x; // 384 = 12 warps
    int h = tid >> 5, lane = tid & 31;
    int e = g_eidx[row * H_ + h];
    const float* wv = Wv + (size_t)(h * E_ + e) * DH_ * DH_;
    const float* xh = g_xln + (size_t)row * D_ + h * DH_;
    float a0 = 0.f, a1 = 0.f;
    for (int d = 0; d < DH_; d++) {
        float xv = xh[d];
        a0 += xv * wv[d * DH_ + lane];
        a1 += xv * wv[d * DH_ + lane + 32];
    }
    g_vsel[(size_t)row * D_ + h * DH_ + lane]      = a0;
    g_vsel[(size_t)row * D_ + h * DH_ + lane + 32] = a1;
}

__global__ void osel_kernel(const float* __restrict__ Wo, const float* __restrict__ x) {
    int row = blockIdx.x, tid = threadIdx.x; // 384
    int h = tid >> 5, lane = tid & 31;
    int e = g_eidx[row * H_ + h];
    const float* wo = Wo + (size_t)(h * E_ + e) * DH_ * DH_;
    const float* af = g_attn + (size_t)row * D_ + h * DH_;
    float a0 = 0.f, a1 = 0.f;
    for (int f = 0; f < DH_; f++) {
        float av = af[f];
        a0 += av * wo[f * DH_ + lane];
        a1 += av * wo[f * DH_ + lane + 32];
    }
    size_t o0 = (size_t)row * D_ + h * DH_ + lane;
    g_x1[o0]      = x[o0]      + a0;
    g_x1[o0 + 32] = x[o0 + 32] + a1;
}

// ---------------- attention pass 1: exact softmax row stats (m_s, l_s) --------
__global__ void attn_pass1() {
    int s0 = blockIdx.x * 64;
    int h = blockIdx.y, b = blockIdx.z;
    int tid = threadIdx.x;
    __shared__ float Qs[64][65];
    __shared__ float Ks[64][65];
    __shared__ float red[64][16];
    __shared__ float sm[64], sl[64], sal[64];
    const float* qb = g_q + (size_t)b * S_ * D_ + h * DH_;
    const float* kb = g_k + (size_t)b * S_ * D_ + h * DH_;
#pragma unroll
    for (int i = 0; i < 16; i++) {
        int idx = tid + i * 256; int r = idx >> 6, d = idx & 63;
        Qs[r][d] = qb[(size_t)(s0 + r) * D_ + d];
    }
    if (tid < 64) { sm[tid] = -INFINITY; sl[tid] = 0.f; }
    __syncthreads();
    int rm = tid >> 4, cn = tid & 15;
    for (int t0 = 0; t0 <= s0; t0 += 64) {
#pragma unroll
        for (int i = 0; i < 16; i++) {
            int idx = tid + i * 256; int r = idx >> 6, d = idx & 63;
            Ks[r][d] = kb[(size_t)(t0 + r) * D_ + d];
        }
        __syncthreads();
        float sv[4][4] = {};
        for (int d = 0; d < 64; d++) {
            float qa[4], ka[4];
#pragma unroll
            for (int i = 0; i < 4; i++) qa[i] = Qs[rm * 4 + i][d];
#pragma unroll
            for (int j = 0; j < 4; j++) ka[j] = Ks[cn * 4 + j][d];
#pragma unroll
            for (int i = 0; i < 4; i++)
#pragma unroll
                for (int j = 0; j < 4; j++) sv[i][j] += qa[i] * ka[j];
        }
#pragma unroll
        for (int i = 0; i < 4; i++) {
            int gs = s0 + rm * 4 + i;
            float mx = -INFINITY;
#pragma unroll
            for (int j = 0; j < 4; j++) {
                int gt = t0 + cn * 4 + j;
                sv[i][j] = sv[i][j] * 0.125f + ((gt <= gs) ? 0.f : -1e9f);
                mx = fmaxf(mx, sv[i][j]);
            }
            red[rm * 4 + i][cn] = mx;
        }
        __syncthreads();
        if (tid < 64) {
            float mt = red[tid][0];
            for (int c = 1; c < 16; c++) mt = fmaxf(mt, red[tid][c]);
            float mo = sm[tid], mn = fmaxf(mo, mt);
            sm[tid] = mn; sal[tid] = expf(mo - mn);
        }
        __syncthreads();
#pragma unroll
        for (int i = 0; i < 4; i++) {
            float m = sm[rm * 4 + i];
            float s = 0.f;
#pragma unroll
            for (int j = 0; j < 4; j++) s += expf(sv[i][j] - m);
            red[rm * 4 + i][cn] = s;
        }
        __syncthreads();
        if (tid < 64) {
            float s = 0.f;
            for (int c = 0; c < 16; c++) s += red[tid][c];
            sl[tid] = sl[tid] * sal[tid] + s;
        }
        __syncthreads();
    }
    if (tid < 64) {
        int o = (b * H_ + h) * S_ + s0 + tid;
        g_m[o] = sm[tid]; g_l[o] = sl[tid];
    }
}

// ---------------- attention pass 2: out[t] = sum_{s>=t} P[s,t] * v[s] ---------
__global__ void attn_pass2() {
    extern __shared__ float dsm[];
    float (*Ks)[65] = (float(*)[65])dsm;
    float (*Qs)[65] = (float(*)[65])(dsm + 64 * 65);
    float (*Vs)[65] = (float(*)[65])(dsm + 2 * 64 * 65);
    float (*Ps)[65] = (float(*)[65])(dsm + 3 * 64 * 65);
    float* srm  = dsm + 4 * 64 * 65;
    float* sinv = srm + 64;
    int t0 = blockIdx.x * 64;
    int h = blockIdx.y, b = blockIdx.z;
    int tid = threadIdx.x;
    const float* qb = g_q    + (size_t)b * S_ * D_ + h * DH_;
    const float* kb = g_k    + (size_t)b * S_ * D_ + h * DH_;
    const float* vb = g_vsel + (size_t)b * S_ * D_ + h * DH_;
#pragma unroll
    for (int i = 0; i < 16; i++) {
        int idx = tid + i * 256; int r = idx >> 6, d = idx & 63;
        Ks[r][d] = kb[(size_t)(t0 + r) * D_ + d];
    }
    float O[4][4] = {};
    int sr = tid >> 4, tn = tid & 15;
    for (int st0 = t0; st0 < S_; st0 += 64) {
#pragma unroll
        for (int i = 0; i < 16; i++) {
            int idx = tid + i * 256; int r = idx >> 6, d = idx & 63;
            Qs[r][d] = qb[(size_t)(st0 + r) * D_ + d];
            Vs[r][d] = vb[(size_t)(st0 + r) * D_ + d];
        }
        if (tid < 64) {
            int o = (b * H_ + h) * S_ + st0 + tid;
            srm[tid] = g_m[o]; sinv[tid] = 1.f / g_l[o];
        }
        __syncthreads();
        float sv[4][4] = {};
        for (int d = 0; d < 64; d++) {
            float qa[4], ka[4];
#pragma unroll
            for (int i = 0; i < 4; i++) qa[i] = Qs[sr * 4 + i][d];
#pragma unroll
            for (int j = 0; j < 4; j++) ka[j] = Ks[tn * 4 + j][d];
#pragma unroll
            for (int i = 0; i < 4; i++)
#pragma unroll
                for (int j = 0; j < 4; j++) sv[i][j] += qa[i] * ka[j];
        }
#pragma unroll
        for (int i = 0; i < 4; i++) {
            int gs = st0 + sr * 4 + i;
            float m = srm[sr * 4 + i], iv = sinv[sr * 4 + i];
#pragma unroll
            for (int j = 0; j < 4; j++) {
                int gt = t0 + tn * 4 + j;
                float p = (gt <= gs) ? expf(sv[i][j] * 0.125f - m) * iv : 0.f;
                Ps[sr * 4 + i][tn * 4 + j] = p;
            }
        }
        __syncthreads();
        for (int s = 0; s < 64; s++) {
            float pv[4], vv[4];
#pragma unroll
            for (int i = 0; i < 4; i++) pv[i] = Ps[s][sr * 4 + i];
#pragma unroll
            for (int j = 0; j < 4; j++) vv[j] = Vs[s][tn * 4 + j];
#pragma unroll
            for (int i = 0; i < 4; i++)
#pragma unroll
                for (int j = 0; j < 4; j++) O[i][j] += pv[i] * vv[j];
        }
        __syncthreads();
    }
#pragma unroll
    for (int i = 0; i < 4; i++)
#pragma unroll
        for (int j = 0; j < 4; j++)
            g_attn[(size_t)(b * S_ + t0 + sr * 4 + i) * D_ + h * DH_ + tn * 4 + j] = O[i][j];
}

// ---------------- FFN gate + top-2 -------------------------------------------
__global__ void gate_kernel(const float* __restrict__ gff) {
    int row = blockIdx.x, tid = threadIdx.x; // 256 = 8 warps
    int w = tid >> 5, lane = tid & 31;
    __shared__ float lg[E_];
    if (w < E_) {
        float acc = 0.f;
        for (int d = lane; d < D_; d += 32)
            acc += g_xln2[(size_t)row * D_ + d] * gff[(size_t)d * E_ + w];
        for (int o = 16; o > 0; o >>= 1) acc += __shfl_down_sync(0xffffffffu, acc, o);
        if (lane == 0) lg[w] = acc;
    }
    __syncthreads();
    if (tid == 0) {
        int i0 = 0; float v0 = lg[0];
        for (int e = 1; e < E_; e++) if (lg[e] > v0) { v0 = lg[e]; i0 = e; }
        int i1 = -1; float v1 = -3.4e38f;
        for (int e = 0; e < E_; e++) { if (e == i0) continue; if (lg[e] > v1) { v1 = lg[e]; i1 = e; } }
        float e1 = expf(v1 - v0);
        float z = 1.f + e1;
        g_tk_idx[row * 2] = i0; g_tk_idx[row * 2 + 1] = i1;
        g_tk_prob[row * 2] = 1.f / z; g_tk_prob[row * 2 + 1] = e1 / z;
    }
}

// ---------------- capacity + deterministic slot assignment --------------------
__global__ void capacity_kernel() {
    int tid = threadIdx.x; // 256 = 8 warps, warp per expert
    int w = tid >> 5, lane = tid & 31;
    if (w < E_) {
        int e = w, c = 0;
        for (int i0 = 0; i0 < NTOK * 2; i0 += 32) {
            int i = i0 + lane;
            int idx = g_tk_idx[i];
            bool match = (idx == e);
            unsigned msk = __ballot_sync(0xffffffffu, match);
            if (match) {
                int rank = c + __popc(msk & ((1u << lane) - 1u));
                if (rank < CAP_) {
                    g_slot_token[e * CAP_ + rank] = i >> 1;
                    g_token_slot[i] = e * CAP_ + rank;
                } else {
                    g_token_slot[i] = -1;
                }
            }
            c += __popc(msk);
        }
        if (lane == 0) g_ecount[e] = (c < CAP_) ? c : CAP_;
    }
    __syncthreads();
    for (int t = tid; t < NTOK; t += 256) {
        int s0 = g_token_slot[2 * t], s1 = g_token_slot[2 * t + 1];
        float p0 = (s0 >= 0) ? g_tk_prob[2 * t]     : 0.f;
        float p1 = (s1 >= 0) ? g_tk_prob[2 * t + 1] : 0.f;
        float inv = 1.f / (p0 + p1 + 1e-9f);
        if (s0 >= 0) g_slot_w[s0] = p0 * inv;
        if (s1 >= 0) g_slot_w[s1] = p1 * inv;
    }
}

// ---------------- FFN GEMM1 (gathered rows, relu) -----------------------------
__global__ void ffn_gemm1(const float* __restrict__ W1) {
    int e = blockIdx.z;
    int count = g_ecount[e];
    int m0 = blockIdx.y * 64;
    if (m0 >= count) return;
    int n0 = blockIdx.x * 64;
    const float* Bm = W1 + (size_t)e * D_ * DFF_;
    __shared__ float As[16][65];
    __shared__ float Bs[16][64];
    int tid = threadIdx.x;
    int rm = tid >> 4, cn = tid & 15;
    int ar = tid >> 2, ac = (tid & 3) << 2;
    int br = tid >> 4, bc = (tid & 15) << 2;
    int arow = m0 + ar;
    const float* Arow = (arow < count) ? (g_xln2 + (size_t)g_slot_token[e * CAP_ + arow] * D_) : nullptr;
    float acc[4][4] = {};
    for (int k0 = 0; k0 < D_; k0 += 16) {
        float4 a = Arow ? *(const float4*)(Arow + k0 + ac) : make_float4(0.f, 0.f, 0.f, 0.f);
        As[ac + 0][ar] = a.x; As[ac + 1][ar] = a.y;
        As[ac + 2][ar] = a.z; As[ac + 3][ar] = a.w;
        *(float4*)&Bs[br][bc] = *(const float4*)(Bm + (size_t)(k0 + br) * DFF_ + n0 + bc);
        __syncthreads();
#pragma unroll
        for (int k = 0; k < 16; k++) {
            float ra[4];
#pragma unroll
            for (int i = 0; i < 4; i++) ra[i] = As[k][rm * 4 + i];
            float4 b4 = *(float4*)&Bs[k][cn * 4];
            float rb[4] = { b4.x, b4.y, b4.z, b4.w };
#pragma unroll
            for (int i = 0; i < 4; i++)
#pragma unroll
                for (int j = 0; j < 4; j++) acc[i][j] += ra[i] * rb[j];
        }
        __syncthreads();
    }
#pragma unroll
    for (int i = 0; i < 4; i++) {
        int m = m0 + rm * 4 + i;
        if (m < count)
#pragma unroll
            for (int j = 0; j < 4; j++)
                g_hbuf[(size_t)(e * CAP_ + m) * DFF_ + n0 + cn * 4 + j] = fmaxf(acc[i][j], 0.f);
    }
}

// ---------------- FFN GEMM2 (scaled by slot weight) ---------------------------
__global__ void ffn_gemm2(const float* __restrict__ W2) {
    int e = blockIdx.z;
    int count = g_ecount[e];
    int m0 = blockIdx.y * 64;
    if (m0 >= count) return;
    int n0 = blockIdx.x * 64;
    const float* Am = g_hbuf + (size_t)e * CAP_ * DFF_;
    const float* Bm = W2 + (size_t)e * DFF_ * D_;
    __shared__ float As[16][65];
    __shared__ float Bs[16][64];
    int tid = threadIdx.x;
    int rm = tid >> 4, cn = tid & 15;
    int ar = tid >> 2, ac = (tid & 3) << 2;
    int br = tid >> 4, bc = (tid & 15) << 2;
    float acc[4][4] = {};
    for (int k0 = 0; k0 < DFF_; k0 += 16) {
        float4 a = *(const float4*)(Am + (size_t)(m0 + ar) * DFF_ + k0 + ac);
        As[ac + 0][ar] = a.x; As[ac + 1][ar] = a.y;
        As[ac + 2][ar] = a.z; As[ac + 3][ar] = a.w;
        *(float4*)&Bs[br][bc] = *(const float4*)(Bm + (size_t)(k0 + br) * D_ + n0 + bc);
        __syncthreads();
#pragma unroll
        for (int k = 0; k < 16; k++) {
            float ra[4];
#pragma unroll
            for (int i = 0; i < 4; i++) ra[i] = As[k][rm * 4 + i];
            float4 b4 = *(float4*)&Bs[k][cn * 4];
            float rb[4] = { b4.x, b4.y, b4.z, b4.w };
#pragma unroll
            for (int i = 0; i < 4; i++)
#pragma unroll
                for (int j = 0; j < 4; j++) acc[i][j] += ra[i] * rb[j];
        }
        __syncthreads();
    }
#pragma unroll
    for (int i = 0; i < 4; i++) {
        int m = m0 + rm * 4 + i;
        if (m < count) {
            float wgt = g_slot_w[e * CAP_ + m];
#pragma unroll
            for (int j = 0; j < 4; j++)
                g_sout[(size_t)(e * CAP_ + m) * D_ + n0 + cn * 4 + j] = wgt * acc[i][j];
        }
    }
}

// ---------------- combine: out = x1 + f (deterministic, atomic-free) ----------
__global__ void combine_kernel(float* __restrict__ out) {
    int row = blockIdx.x, tid = threadIdx.x;
    int s0 = g_token_slot[2 * row], s1 = g_token_slot[2 * row + 1];
    for (int d = tid; d < D_; d += 256) {
        float v = g_x1[(size_t)row * D_ + d];
        if (s0 >= 0) v += g_sout[(size_t)s0 * D_ + d];
        if (s1 >= 0) v += g_sout[(size_t)s1 * D_ + d];
        out[(size_t)row * D_ + d] = v;
    }
}

// ---------------- aux losses ---------------------------------------------------
__global__ void aux_kernel(float* __restrict__ out, int out_size) {
    __shared__ float sa;
    if (threadIdx.x == 0) {
        const float scale = 0.01f / 2048.f;
        float es = 0.f;
        for (int i = 0; i < H_ * E_; i++) es += g_hard[i] * scale;
        float a1 = 0.f;
        for (int i = 0; i < H_ * E_; i++) {
            float p = (g_hard[i] * scale) / (es + 1e-9f);
            a1 += p * p;
        }
        a1 *= (float)(E_ * H_);
        float tcs = 0.f, ics = 0.f, ic[E_];
        for (int e = 0; e < E_; e++) {
            float s = 0.f; int c = g_ecount[e];
            for (int r = 0; r < c; r++) s += g_slot_w[e * CAP_ + r];
            ic[e] = s; ics += s; tcs += (float)c;
        }
        float a2 = 0.f;
        for (int e = 0; e < E_; e++) a2 += ((float)g_ecount[e] / tcs) * (ic[e] / ics);
        a2 *= (float)E_;
        sa = a1 + a2;
    }
    __syncthreads();
    for (int i = NOUT + threadIdx.x; i < out_size; i += blockDim.x) out[i] = sa;
}

// ---------------- launch -------------------------------------------------------
extern "C" void kernel_launch(void* const* d_in, const int* in_sizes, int n_in,
                              void* d_out, int out_size) {
    const float* x   = (const float*)d_in[0];
    // d_in[1] = mask (pure causal 0/-1e9, applied analytically)
    const float* Wq  = (const float*)d_in[2];
    const float* Wk  = (const float*)d_in[3];
    const float* Wv  = (const float*)d_in[4];
    const float* Wo  = (const float*)d_in[5];
    const float* Wr  = (const float*)d_in[6];
    const float* g1  = (const float*)d_in[7];
    const float* b1  = (const float*)d_in[8];
    const float* g2  = (const float*)d_in[9];
    const float* b2  = (const float*)d_in[10];
    const float* gff = (const float*)d_in[11];
    const float* W1  = (const float*)d_in[12];
    const float* W2  = (const float*)d_in[13];
    float* out = (float*)d_out;

    float *p_xln, *p_q, *p_k, *p_x1, *p_xln2;
    cudaGetSymbolAddress((void**)&p_xln,  g_xln);
    cudaGetSymbolAddress((void**)&p_q,    g_q);
    cudaGetSymbolAddress((void**)&p_k,    g_k);
    cudaGetSymbolAddress((void**)&p_x1,   g_x1);
    cudaGetSymbolAddress((void**)&p_xln2, g_xln2);

    const int pass2_smem = (4 * 64 * 65 + 128) * (int)sizeof(float);
    cudaFuncSetAttribute(attn_pass2, cudaFuncAttributeMaxDynamicSharedMemorySize, pass2_smem);

    zero_hard<<<1, 128>>>();
    ln_kernel<<<NTOK, 256>>>(x, g1, b1, p_xln);
    sgemm_nn<<<dim3(D_ / 64, NTOK / 64), 256>>>(p_xln, Wq, p_q, NTOK, D_, D_);
    sgemm_nn<<<dim3(D_ / 64, NTOK / 64), 256>>>(p_xln, Wk, p_k, NTOK, D_, D_);
    router_kernel<<<NTOK, 128>>>(Wr);
    vsel_kernel<<<NTOK, 384>>>(Wv);
    attn_pass1<<<dim3(S_ / 64, H_, B_), 256>>>();
    attn_pass2<<<dim3(S_ / 64, H_, B_), 256, pass2_smem>>>();
    osel_kernel<<<NTOK, 384>>>(Wo, x);
    ln_kernel<<<NTOK, 256>>>(p_x1, g2, b2, p_xln2);
    gate_kernel<<<NTOK, 256>>>(gff);
    capacity_kernel<<<1, 256>>>();
    ffn_gemm1<<<dim3(DFF_ / 64, CAP_ / 64, E_), 256>>>(W1);
    ffn_gemm2<<<dim3(D_ / 64, CAP_ / 64, E_), 256>>>(W2);
    combine_kernel<<<NTOK, 256>>>(out);
    if (out_size > NOUT) aux_kernel<<<1, 256>>>(out, out_size);
}